// round 12
// baseline (speedup 1.0000x reference)
#include <cuda_runtime.h>

// MatchNet: per-row MLP(6->20->20->20->8, tanh) + 150-iter PDHG LP.
// R12 = R11 with the phase-locked serialization window shrunk:
//  - c2 = max(0, fma(-2*TCC, rr, 2)) computed alongside scale; xb = fma(c2,d,zm)
//    (removes scale->ns->xb two-step from the rr-window).
//  - ||d||^2 as two 4-long chains + final add (chain 20 cyc vs 32 serial).
// Body otherwise identical to R11/R9 (89-ish fma ops/iter).

#define NTHREADS 32
#define PDHG_ITERS 150

#define TAU   0.18898223650461357f   /* 1/sqrt(28) */
#define SGM   0.18898223650461357f   /* sigma = tau */
#define TCC   1.8898223650461357f    /* tau * control_strength(10) */
#define TCC2  3.7796447300922714f    /* 2 * TCC */

typedef unsigned long long u64;

__device__ __forceinline__ u64 pk(float a, float b) {
    u64 r; asm("mov.b64 %0, {%1, %2};" : "=l"(r) : "f"(a), "f"(b)); return r;
}
__device__ __forceinline__ void upk(float& a, float& b, u64 p) {
    asm("mov.b64 {%0, %1}, %2;" : "=f"(a), "=f"(b) : "l"(p));
}
__device__ __forceinline__ u64 fma2(u64 a, u64 b, u64 c) {
    u64 d; asm("fma.rn.f32x2 %0, %1, %2, %3;" : "=l"(d) : "l"(a), "l"(b), "l"(c)); return d;
}
__device__ __forceinline__ float fast_rsqrt(float v) {
    float r; asm("rsqrt.approx.f32 %0, %1;" : "=f"(r) : "f"(v)); return r;
}
__device__ __forceinline__ float fast_tanh(float x) {
    float e = __expf(2.0f * x);
    return 1.0f - __fdividef(2.0f, e + 1.0f);
}

__global__ __launch_bounds__(NTHREADS)
void matchnet_kernel(
    const float* __restrict__ X,
    const float* __restrict__ W1, const float* __restrict__ b1,
    const float* __restrict__ W2, const float* __restrict__ b2,
    const float* __restrict__ W3, const float* __restrict__ b3,
    const float* __restrict__ W4, const float* __restrict__ b4,
    float* __restrict__ out, int B)
{
    __shared__ __align__(16) float sW1[120], sW2[400], sW3[400], sW4[160];
    __shared__ __align__(16) float sb1[20], sb2[20], sb3[20], sb4[8];

    const int t = threadIdx.x;
    for (int i = t; i < 120; i += NTHREADS) sW1[i] = W1[i];
    for (int i = t; i < 400; i += NTHREADS) sW2[i] = W2[i];
    for (int i = t; i < 400; i += NTHREADS) sW3[i] = W3[i];
    for (int i = t; i < 160; i += NTHREADS) sW4[i] = W4[i];
    if (t < 20) { sb1[t] = b1[t]; sb2[t] = b2[t]; sb3[t] = b3[t]; }
    if (t < 8)  { sb4[t] = b4[t]; }
    __syncthreads();

    const int row = blockIdx.x * NTHREADS + t;
    if (row >= B) return;

    // ---- input row (RHS b of the LP) ----
    float Z0, Z1, Z2, Z3, Z4, Z5;
    {
        const float2* p = (const float2*)(X + row * 6);
        float2 a0 = p[0], a1 = p[1], a2 = p[2];
        Z0 = a0.x; Z1 = a0.y; Z2 = a1.x;
        Z3 = a1.y; Z4 = a2.x; Z5 = a2.y;
    }

    // ---- MLP, f32x2-packed (validated R6-R11) ----
    float h[20], h2[20];
    {
        float Zv[6] = {Z0, Z1, Z2, Z3, Z4, Z5};
        u64 a[10];
#pragma unroll
        for (int jp = 0; jp < 10; jp++) a[jp] = *(const u64*)&sb1[2 * jp];
#pragma unroll
        for (int k = 0; k < 6; k++) {
            u64 zz = pk(Zv[k], Zv[k]);
#pragma unroll
            for (int jp = 0; jp < 10; jp++)
                a[jp] = fma2(zz, *(const u64*)&sW1[k * 20 + 2 * jp], a[jp]);
        }
#pragma unroll
        for (int jp = 0; jp < 10; jp++) {
            float s0, s1; upk(s0, s1, a[jp]);
            h[2 * jp] = fast_tanh(s0); h[2 * jp + 1] = fast_tanh(s1);
        }
    }
    {
        u64 a[10];
#pragma unroll
        for (int jp = 0; jp < 10; jp++) a[jp] = *(const u64*)&sb2[2 * jp];
#pragma unroll
        for (int k = 0; k < 20; k++) {
            u64 hh = pk(h[k], h[k]);
#pragma unroll
            for (int jp = 0; jp < 10; jp++)
                a[jp] = fma2(hh, *(const u64*)&sW2[k * 20 + 2 * jp], a[jp]);
        }
#pragma unroll
        for (int jp = 0; jp < 10; jp++) {
            float s0, s1; upk(s0, s1, a[jp]);
            h2[2 * jp] = fast_tanh(s0); h2[2 * jp + 1] = fast_tanh(s1);
        }
    }
    {
        u64 a[10];
#pragma unroll
        for (int jp = 0; jp < 10; jp++) a[jp] = *(const u64*)&sb3[2 * jp];
#pragma unroll
        for (int k = 0; k < 20; k++) {
            u64 hh = pk(h2[k], h2[k]);
#pragma unroll
            for (int jp = 0; jp < 10; jp++)
                a[jp] = fma2(hh, *(const u64*)&sW3[k * 20 + 2 * jp], a[jp]);
        }
#pragma unroll
        for (int jp = 0; jp < 10; jp++) {
            float s0, s1; upk(s0, s1, a[jp]);
            h[2 * jp] = fast_tanh(s0); h[2 * jp + 1] = fast_tanh(s1);
        }
    }
    float z[8];
    {
        u64 a[4];
#pragma unroll
        for (int jp = 0; jp < 4; jp++) a[jp] = *(const u64*)&sb4[2 * jp];
#pragma unroll
        for (int k = 0; k < 20; k++) {
            u64 hh = pk(h[k], h[k]);
#pragma unroll
            for (int jp = 0; jp < 4; jp++)
                a[jp] = fma2(hh, *(const u64*)&sW4[k * 8 + 2 * jp], a[jp]);
        }
#pragma unroll
        for (int jp = 0; jp < 4; jp++) upk(z[2 * jp], z[2 * jp + 1], a[jp]);
    }

    // ---- PDHG state init (no prologue; loop iter 1 == reference step 1) ----
    float sdn0, sdn1, sdn2, sdn3, sdn4, sdn5, sdn6, sdn7;
    float xb0, xb1, xb2, xb3, xb4, xb5, xb6, xb7;
    float zm0, zm1, zm2, zm3, zm4, zm5, zm6, zm7;
    {
        float x00 = fmaxf(z[0], 0.0f), x01 = fmaxf(z[1], 0.0f);
        float x02 = fmaxf(z[2], 0.0f), x03 = fmaxf(z[3], 0.0f);
        float x04 = fmaxf(z[4], 0.0f), x05 = fmaxf(z[5], 0.0f);
        float x06 = fmaxf(z[6], 0.0f), x07 = fmaxf(z[7], 0.0f);
        sdn0 = x00 - z[0]; sdn1 = x01 - z[1]; sdn2 = x02 - z[2]; sdn3 = x03 - z[3];
        sdn4 = x04 - z[4]; sdn5 = x05 - z[5]; sdn6 = x06 - z[6]; sdn7 = x07 - z[7];
        xb0 = x00; xb1 = x01; xb2 = x02; xb3 = x03;
        xb4 = x04; xb5 = x05; xb6 = x06; xb7 = x07;
        zm0 = z[0] - sdn0; zm1 = z[1] - sdn1; zm2 = z[2] - sdn2; zm3 = z[3] - sdn3;
        zm4 = z[4] - sdn4; zm5 = z[5] - sdn5; zm6 = z[6] - sdn6; zm7 = z[7] - sdn7;
    }
    float y0 = 0.f, y1 = 0.f, y2 = 0.f, y3 = 0.f, y4 = 0.f, y5 = 0.f;
    float w0 = 1.f, w1 = 1.f, w2 = 1.f, w3 = 1.f,   // YIp = yI + 1
          w4 = 1.f, w5 = 1.f, w6 = 1.f, w7 = 1.f;

#pragma unroll 2
    for (int it = 0; it < PDHG_ITERS; it++) {
        // ---- s = S*xb - Z via shared pairs (17 adds; R11) ----
        float A  = xb2 + xb5;
        float Bp = xb1 + xb4;
        float C  = xb0 + xb6;
        float s0 = ((xb0 + xb7) - Z0) + A;     // {0,2,5,7}
        float s1 = Bp + (xb3 - Z1);            // {1,3,4}
        float s2 = C + (xb1 - Z2);             // {0,1,6}
        float s3 = A + (xb3 - Z3);             // {2,3,5}
        float s4 = (Bp - Z4) + (xb2 + xb7);    // {1,2,4,7}
        float s5 = C + (xb4 - Z5);             // {0,4,6}

        // ---- dual updates ----
        y0 = fmaxf(0.0f, fmaf(SGM, s0, y0));
        y1 = fmaxf(0.0f, fmaf(SGM, s1, y1));
        y2 = fmaxf(0.0f, fmaf(SGM, s2, y2));
        y3 = fmaxf(0.0f, fmaf(SGM, s3, y3));
        y4 = fmaxf(0.0f, fmaf(SGM, s4, y4));
        y5 = fmaxf(0.0f, fmaf(SGM, s5, y5));

        w0 = fmaxf(1.0f, fmaf(-SGM, xb0, w0));
        w1 = fmaxf(1.0f, fmaf(-SGM, xb1, w1));
        w2 = fmaxf(1.0f, fmaf(-SGM, xb2, w2));
        w3 = fmaxf(1.0f, fmaf(-SGM, xb3, w3));
        w4 = fmaxf(1.0f, fmaf(-SGM, xb4, w4));
        w5 = fmaxf(1.0f, fmaf(-SGM, xb5, w5));
        w6 = fmaxf(1.0f, fmaf(-SGM, xb6, w6));
        w7 = fmaxf(1.0f, fmaf(-SGM, xb7, w7));

        // ---- gy = S^T y - YIp (q-reuse) ----
        float q25 = y2 + y5, q04 = y0 + y4, q14 = y1 + y4;
        float gy0 = (y0 + q25) - w0;
        float gy1 = (q14 + y2) - w1;
        float gy2 = (q04 + y3) - w2;
        float gy3 = (y1 + y3) - w3;
        float gy4 = (q14 + y5) - w4;
        float gy5 = (y0 + y3) - w5;
        float gy6 = q25 - w6;
        float gy7 = q04 - w7;

        // ---- d = sdn - tau*gy ----
        float d0 = fmaf(-TAU, gy0, sdn0);
        float d1 = fmaf(-TAU, gy1, sdn1);
        float d2 = fmaf(-TAU, gy2, sdn2);
        float d3 = fmaf(-TAU, gy3, sdn3);
        float d4 = fmaf(-TAU, gy4, sdn4);
        float d5 = fmaf(-TAU, gy5, sdn5);
        float d6 = fmaf(-TAU, gy6, sdn6);
        float d7 = fmaf(-TAU, gy7, sdn7);

        // ---- ||d||^2: two 4-chains + add (chain ~20 cyc, 9 ops) ----
        float na = d0 * d0;
        na = fmaf(d1, d1, na);
        na = fmaf(d2, d2, na);
        na = fmaf(d3, d3, na);
        float nb = d4 * d4;
        nb = fmaf(d5, d5, nb);
        nb = fmaf(d6, d6, nb);
        nb = fmaf(d7, d7, nb);
        float nn = na + nb;
        float rr = fast_rsqrt(nn);   // nn=0 -> rr=inf -> scale,c2=0 (exact)

        // ---- scale family straight off rr (parallel) ----
        float scale = fmaxf(0.0f, fmaf(-TCC,  rr, 1.0f));
        float c2    = fmaxf(0.0f, fmaf(-TCC2, rr, 2.0f));   // = 2*scale

        // ---- primal: xb = c2*d + zm (chain-short path);
        //      ns = scale*d; zm = z - ns; sdn = ns (off-chain) ----
        xb0 = fmaf(c2, d0, zm0);
        xb1 = fmaf(c2, d1, zm1);
        xb2 = fmaf(c2, d2, zm2);
        xb3 = fmaf(c2, d3, zm3);
        xb4 = fmaf(c2, d4, zm4);
        xb5 = fmaf(c2, d5, zm5);
        xb6 = fmaf(c2, d6, zm6);
        xb7 = fmaf(c2, d7, zm7);

        float ns0 = scale * d0, ns1 = scale * d1, ns2 = scale * d2, ns3 = scale * d3;
        float ns4 = scale * d4, ns5 = scale * d5, ns6 = scale * d6, ns7 = scale * d7;
        zm0 = z[0] - ns0; sdn0 = ns0;
        zm1 = z[1] - ns1; sdn1 = ns1;
        zm2 = z[2] - ns2; sdn2 = ns2;
        zm3 = z[3] - ns3; sdn3 = ns3;
        zm4 = z[4] - ns4; sdn4 = ns4;
        zm5 = z[5] - ns5; sdn5 = ns5;
        zm6 = z[6] - ns6; sdn6 = ns6;
        zm7 = z[7] - ns7; sdn7 = ns7;
    }

    // ---- x = z + sdn ----
    float4* p = (float4*)(out + row * 8);
    p[0] = make_float4(z[0] + sdn0, z[1] + sdn1, z[2] + sdn2, z[3] + sdn3);
    p[1] = make_float4(z[4] + sdn4, z[5] + sdn5, z[6] + sdn6, z[7] + sdn7);
}

extern "C" void kernel_launch(void* const* d_in, const int* in_sizes, int n_in,
                              void* d_out, int out_size) {
    const float* X  = (const float*)d_in[0];
    const float* W1 = (const float*)d_in[1];
    const float* b1 = (const float*)d_in[2];
    const float* W2 = (const float*)d_in[3];
    const float* b2 = (const float*)d_in[4];
    const float* W3 = (const float*)d_in[5];
    const float* b3 = (const float*)d_in[6];
    const float* W4 = (const float*)d_in[7];
    const float* b4 = (const float*)d_in[8];

    const int B = in_sizes[0] / 6;
    const int grid = (B + NTHREADS - 1) / NTHREADS;
    matchnet_kernel<<<grid, NTHREADS>>>(X, W1, b1, W2, b2, W3, b3, W4, b4,
                                        (float*)d_out, B);
}

// round 13
// speedup vs baseline: 1.1415x; 1.1415x over previous
#include <cuda_runtime.h>

// MatchNet: per-row MLP(6->20->20->20->8, tanh) + 150-iter PDHG LP.
// R13 = R11 body + anti-phase stagger. 256-thr blocks: warps w and w+4 share
// an SMSP (wid%4). Warps 4-7 run a ~225-cyc dependent-FMA delay before the
// PDHG loop so the two co-resident warps hit the rsqrt/scale serialization
// window in anti-phase; each warp's stall is covered by the partner's fma
// stream. (Phase-lock hypothesis: 356 pipe-cyc/iter demand vs 450 measured.)

#define NTHREADS 256
#define PDHG_ITERS 150

#define TAU  0.18898223650461357f   /* 1/sqrt(28) */
#define SGM  0.18898223650461357f   /* sigma = tau */
#define TCC  1.8898223650461357f    /* tau * control_strength(10) */

typedef unsigned long long u64;

__device__ __forceinline__ u64 pk(float a, float b) {
    u64 r; asm("mov.b64 %0, {%1, %2};" : "=l"(r) : "f"(a), "f"(b)); return r;
}
__device__ __forceinline__ void upk(float& a, float& b, u64 p) {
    asm("mov.b64 {%0, %1}, %2;" : "=f"(a), "=f"(b) : "l"(p));
}
__device__ __forceinline__ u64 fma2(u64 a, u64 b, u64 c) {
    u64 d; asm("fma.rn.f32x2 %0, %1, %2, %3;" : "=l"(d) : "l"(a), "l"(b), "l"(c)); return d;
}
__device__ __forceinline__ float fast_rsqrt(float v) {
    float r; asm("rsqrt.approx.f32 %0, %1;" : "=f"(r) : "f"(v)); return r;
}
__device__ __forceinline__ float fast_tanh(float x) {
    float e = __expf(2.0f * x);
    return 1.0f - __fdividef(2.0f, e + 1.0f);
}

__global__ __launch_bounds__(NTHREADS)
void matchnet_kernel(
    const float* __restrict__ X,
    const float* __restrict__ W1, const float* __restrict__ b1,
    const float* __restrict__ W2, const float* __restrict__ b2,
    const float* __restrict__ W3, const float* __restrict__ b3,
    const float* __restrict__ W4, const float* __restrict__ b4,
    float* __restrict__ out, int B)
{
    __shared__ __align__(16) float sW1[120], sW2[400], sW3[400], sW4[160];
    __shared__ __align__(16) float sb1[20], sb2[20], sb3[20], sb4[8];

    const int t = threadIdx.x;
    for (int i = t; i < 120; i += NTHREADS) sW1[i] = W1[i];
    for (int i = t; i < 400; i += NTHREADS) sW2[i] = W2[i];
    for (int i = t; i < 400; i += NTHREADS) sW3[i] = W3[i];
    for (int i = t; i < 160; i += NTHREADS) sW4[i] = W4[i];
    if (t < 20) { sb1[t] = b1[t]; sb2[t] = b2[t]; sb3[t] = b3[t]; }
    if (t < 8)  { sb4[t] = b4[t]; }
    __syncthreads();

    const int row = blockIdx.x * NTHREADS + t;
    if (row >= B) return;

    // ---- input row (RHS b of the LP) ----
    float Z0, Z1, Z2, Z3, Z4, Z5;
    {
        const float2* p = (const float2*)(X + row * 6);
        float2 a0 = p[0], a1 = p[1], a2 = p[2];
        Z0 = a0.x; Z1 = a0.y; Z2 = a1.x;
        Z3 = a1.y; Z4 = a2.x; Z5 = a2.y;
    }

    // ---- MLP, f32x2-packed (validated R6-R12) ----
    float h[20], h2[20];
    {
        float Zv[6] = {Z0, Z1, Z2, Z3, Z4, Z5};
        u64 a[10];
#pragma unroll
        for (int jp = 0; jp < 10; jp++) a[jp] = *(const u64*)&sb1[2 * jp];
#pragma unroll
        for (int k = 0; k < 6; k++) {
            u64 zz = pk(Zv[k], Zv[k]);
#pragma unroll
            for (int jp = 0; jp < 10; jp++)
                a[jp] = fma2(zz, *(const u64*)&sW1[k * 20 + 2 * jp], a[jp]);
        }
#pragma unroll
        for (int jp = 0; jp < 10; jp++) {
            float s0, s1; upk(s0, s1, a[jp]);
            h[2 * jp] = fast_tanh(s0); h[2 * jp + 1] = fast_tanh(s1);
        }
    }
    {
        u64 a[10];
#pragma unroll
        for (int jp = 0; jp < 10; jp++) a[jp] = *(const u64*)&sb2[2 * jp];
#pragma unroll
        for (int k = 0; k < 20; k++) {
            u64 hh = pk(h[k], h[k]);
#pragma unroll
            for (int jp = 0; jp < 10; jp++)
                a[jp] = fma2(hh, *(const u64*)&sW2[k * 20 + 2 * jp], a[jp]);
        }
#pragma unroll
        for (int jp = 0; jp < 10; jp++) {
            float s0, s1; upk(s0, s1, a[jp]);
            h2[2 * jp] = fast_tanh(s0); h2[2 * jp + 1] = fast_tanh(s1);
        }
    }
    {
        u64 a[10];
#pragma unroll
        for (int jp = 0; jp < 10; jp++) a[jp] = *(const u64*)&sb3[2 * jp];
#pragma unroll
        for (int k = 0; k < 20; k++) {
            u64 hh = pk(h2[k], h2[k]);
#pragma unroll
            for (int jp = 0; jp < 10; jp++)
                a[jp] = fma2(hh, *(const u64*)&sW3[k * 20 + 2 * jp], a[jp]);
        }
#pragma unroll
        for (int jp = 0; jp < 10; jp++) {
            float s0, s1; upk(s0, s1, a[jp]);
            h[2 * jp] = fast_tanh(s0); h[2 * jp + 1] = fast_tanh(s1);
        }
    }
    float z[8];
    {
        u64 a[4];
#pragma unroll
        for (int jp = 0; jp < 4; jp++) a[jp] = *(const u64*)&sb4[2 * jp];
#pragma unroll
        for (int k = 0; k < 20; k++) {
            u64 hh = pk(h[k], h[k]);
#pragma unroll
            for (int jp = 0; jp < 4; jp++)
                a[jp] = fma2(hh, *(const u64*)&sW4[k * 8 + 2 * jp], a[jp]);
        }
#pragma unroll
        for (int jp = 0; jp < 4; jp++) upk(z[2 * jp], z[2 * jp + 1], a[jp]);
    }

    // ---- anti-phase stagger: warps 4-7 (partner SMSP warps) delay ~225 cyc.
    // asm volatile dependent-FMA chain: cannot be elided or reordered away;
    // result unused (dead register), semantics unaffected.
    if ((t >> 5) >= 4) {
        float acc = 1.0f;
#pragma unroll 1
        for (int i = 0; i < 56; i++)
            asm volatile("fma.rn.f32 %0, %0, 0f3F7FFF58, 0f38D1B717;" : "+f"(acc));
    }

    // ---- PDHG state init (R11 body, validated) ----
    float sdn0, sdn1, sdn2, sdn3, sdn4, sdn5, sdn6, sdn7;
    float xb0, xb1, xb2, xb3, xb4, xb5, xb6, xb7;
    float zm0, zm1, zm2, zm3, zm4, zm5, zm6, zm7;
    {
        float x00 = fmaxf(z[0], 0.0f), x01 = fmaxf(z[1], 0.0f);
        float x02 = fmaxf(z[2], 0.0f), x03 = fmaxf(z[3], 0.0f);
        float x04 = fmaxf(z[4], 0.0f), x05 = fmaxf(z[5], 0.0f);
        float x06 = fmaxf(z[6], 0.0f), x07 = fmaxf(z[7], 0.0f);
        sdn0 = x00 - z[0]; sdn1 = x01 - z[1]; sdn2 = x02 - z[2]; sdn3 = x03 - z[3];
        sdn4 = x04 - z[4]; sdn5 = x05 - z[5]; sdn6 = x06 - z[6]; sdn7 = x07 - z[7];
        xb0 = x00; xb1 = x01; xb2 = x02; xb3 = x03;
        xb4 = x04; xb5 = x05; xb6 = x06; xb7 = x07;
        zm0 = z[0] - sdn0; zm1 = z[1] - sdn1; zm2 = z[2] - sdn2; zm3 = z[3] - sdn3;
        zm4 = z[4] - sdn4; zm5 = z[5] - sdn5; zm6 = z[6] - sdn6; zm7 = z[7] - sdn7;
    }
    float y0 = 0.f, y1 = 0.f, y2 = 0.f, y3 = 0.f, y4 = 0.f, y5 = 0.f;
    float w0 = 1.f, w1 = 1.f, w2 = 1.f, w3 = 1.f,   // YIp = yI + 1
          w4 = 1.f, w5 = 1.f, w6 = 1.f, w7 = 1.f;

#pragma unroll 2
    for (int it = 0; it < PDHG_ITERS; it++) {
        // ---- s = S*xb - Z via shared pairs (17 adds) ----
        float A  = xb2 + xb5;
        float Bp = xb1 + xb4;
        float C  = xb0 + xb6;
        float s0 = ((xb0 + xb7) - Z0) + A;     // {0,2,5,7}
        float s1 = Bp + (xb3 - Z1);            // {1,3,4}
        float s2 = C + (xb1 - Z2);             // {0,1,6}
        float s3 = A + (xb3 - Z3);             // {2,3,5}
        float s4 = (Bp - Z4) + (xb2 + xb7);    // {1,2,4,7}
        float s5 = C + (xb4 - Z5);             // {0,4,6}

        // ---- dual updates ----
        y0 = fmaxf(0.0f, fmaf(SGM, s0, y0));
        y1 = fmaxf(0.0f, fmaf(SGM, s1, y1));
        y2 = fmaxf(0.0f, fmaf(SGM, s2, y2));
        y3 = fmaxf(0.0f, fmaf(SGM, s3, y3));
        y4 = fmaxf(0.0f, fmaf(SGM, s4, y4));
        y5 = fmaxf(0.0f, fmaf(SGM, s5, y5));

        w0 = fmaxf(1.0f, fmaf(-SGM, xb0, w0));
        w1 = fmaxf(1.0f, fmaf(-SGM, xb1, w1));
        w2 = fmaxf(1.0f, fmaf(-SGM, xb2, w2));
        w3 = fmaxf(1.0f, fmaf(-SGM, xb3, w3));
        w4 = fmaxf(1.0f, fmaf(-SGM, xb4, w4));
        w5 = fmaxf(1.0f, fmaf(-SGM, xb5, w5));
        w6 = fmaxf(1.0f, fmaf(-SGM, xb6, w6));
        w7 = fmaxf(1.0f, fmaf(-SGM, xb7, w7));

        // ---- gy = S^T y - YIp (q-reuse) ----
        float q25 = y2 + y5, q04 = y0 + y4, q14 = y1 + y4;
        float gy0 = (y0 + q25) - w0;
        float gy1 = (q14 + y2) - w1;
        float gy2 = (q04 + y3) - w2;
        float gy3 = (y1 + y3) - w3;
        float gy4 = (q14 + y5) - w4;
        float gy5 = (y0 + y3) - w5;
        float gy6 = q25 - w6;
        float gy7 = q04 - w7;

        // ---- d = sdn - tau*gy ----
        float d0 = fmaf(-TAU, gy0, sdn0);
        float d1 = fmaf(-TAU, gy1, sdn1);
        float d2 = fmaf(-TAU, gy2, sdn2);
        float d3 = fmaf(-TAU, gy3, sdn3);
        float d4 = fmaf(-TAU, gy4, sdn4);
        float d5 = fmaf(-TAU, gy5, sdn5);
        float d6 = fmaf(-TAU, gy6, sdn6);
        float d7 = fmaf(-TAU, gy7, sdn7);

        // ---- ||d||^2: two 4-chains + add; rsqrt; scale ----
        float na = d0 * d0;
        na = fmaf(d1, d1, na);
        na = fmaf(d2, d2, na);
        na = fmaf(d3, d3, na);
        float nb = d4 * d4;
        nb = fmaf(d5, d5, nb);
        nb = fmaf(d6, d6, nb);
        nb = fmaf(d7, d7, nb);
        float nn = na + nb;
        float rr = fast_rsqrt(nn);   // nn=0 -> rr=inf -> scale=0 (exact)
        float scale = fmaxf(0.0f, fmaf(-TCC, rr, 1.0f));

        // ---- primal: ns = scale*d; xb = 2*ns + zm; zm = z - ns ----
        float ns0 = scale * d0, ns1 = scale * d1, ns2 = scale * d2, ns3 = scale * d3;
        float ns4 = scale * d4, ns5 = scale * d5, ns6 = scale * d6, ns7 = scale * d7;

        xb0 = fmaf(2.0f, ns0, zm0); zm0 = z[0] - ns0; sdn0 = ns0;
        xb1 = fmaf(2.0f, ns1, zm1); zm1 = z[1] - ns1; sdn1 = ns1;
        xb2 = fmaf(2.0f, ns2, zm2); zm2 = z[2] - ns2; sdn2 = ns2;
        xb3 = fmaf(2.0f, ns3, zm3); zm3 = z[3] - ns3; sdn3 = ns3;
        xb4 = fmaf(2.0f, ns4, zm4); zm4 = z[4] - ns4; sdn4 = ns4;
        xb5 = fmaf(2.0f, ns5, zm5); zm5 = z[5] - ns5; sdn5 = ns5;
        xb6 = fmaf(2.0f, ns6, zm6); zm6 = z[6] - ns6; sdn6 = ns6;
        xb7 = fmaf(2.0f, ns7, zm7); zm7 = z[7] - ns7; sdn7 = ns7;
    }

    // ---- x = z + sdn ----
    float4* p = (float4*)(out + row * 8);
    p[0] = make_float4(z[0] + sdn0, z[1] + sdn1, z[2] + sdn2, z[3] + sdn3);
    p[1] = make_float4(z[4] + sdn4, z[5] + sdn5, z[6] + sdn6, z[7] + sdn7);
}

extern "C" void kernel_launch(void* const* d_in, const int* in_sizes, int n_in,
                              void* d_out, int out_size) {
    const float* X  = (const float*)d_in[0];
    const float* W1 = (const float*)d_in[1];
    const float* b1 = (const float*)d_in[2];
    const float* W2 = (const float*)d_in[3];
    const float* b2 = (const float*)d_in[4];
    const float* W3 = (const float*)d_in[5];
    const float* b3 = (const float*)d_in[6];
    const float* W4 = (const float*)d_in[7];
    const float* b4 = (const float*)d_in[8];

    const int B = in_sizes[0] / 6;
    const int grid = (B + NTHREADS - 1) / NTHREADS;
    matchnet_kernel<<<grid, NTHREADS>>>(X, W1, b1, W2, b2, W3, b3, W4, b4,
                                        (float*)d_out, B);
}

// round 14
// speedup vs baseline: 1.1515x; 1.0088x over previous
#include <cuda_runtime.h>

// MatchNet: per-row MLP(6->20->20->20->8, tanh) + 150-iter PDHG LP.
// R14 = R13 (anti-phase stagger, 29.4us) + FADD/FSUB -> FFMA-imm conversion.
// Now that the kernel is pipe-bound (345 cyc/iter ~= 298 predicted pipe +
// overhead), the imm-form rt_SMSP=1 (vs 2 for FADD) cuts the rt-2 residue:
// 42 adds/subs -> rt1, pipe-cyc 149 -> 107 per warp per iter.
// All conversions are exact (x*1.0+y) and keep R13's association order.

#define NTHREADS 256
#define PDHG_ITERS 150

#define TAU  0.18898223650461357f   /* 1/sqrt(28) */
#define SGM  0.18898223650461357f   /* sigma = tau */
#define TCC  1.8898223650461357f    /* tau * control_strength(10) */

typedef unsigned long long u64;

__device__ __forceinline__ u64 pk(float a, float b) {
    u64 r; asm("mov.b64 %0, {%1, %2};" : "=l"(r) : "f"(a), "f"(b)); return r;
}
__device__ __forceinline__ void upk(float& a, float& b, u64 p) {
    asm("mov.b64 {%0, %1}, %2;" : "=f"(a), "=f"(b) : "l"(p));
}
__device__ __forceinline__ u64 fma2(u64 a, u64 b, u64 c) {
    u64 d; asm("fma.rn.f32x2 %0, %1, %2, %3;" : "=l"(d) : "l"(a), "l"(b), "l"(c)); return d;
}
__device__ __forceinline__ float fast_rsqrt(float v) {
    float r; asm("rsqrt.approx.f32 %0, %1;" : "=f"(r) : "f"(v)); return r;
}
__device__ __forceinline__ float fast_tanh(float x) {
    float e = __expf(2.0f * x);
    return 1.0f - __fdividef(2.0f, e + 1.0f);
}
// a + b as FFMA-imm (a*1.0 + b): exact; targets rt_SMSP=1 imm-form.
__device__ __forceinline__ float fai(float a, float b) {
    float r;
    asm("fma.rn.f32 %0, %1, 0f3F800000, %2;" : "=f"(r) : "f"(a), "f"(b));
    return r;
}
// a - b as FFMA-imm (b*(-1.0) + a): exact.
__device__ __forceinline__ float fsi(float a, float b) {
    float r;
    asm("fma.rn.f32 %0, %1, 0fBF800000, %2;" : "=f"(r) : "f"(b), "f"(a));
    return r;
}

__global__ __launch_bounds__(NTHREADS)
void matchnet_kernel(
    const float* __restrict__ X,
    const float* __restrict__ W1, const float* __restrict__ b1,
    const float* __restrict__ W2, const float* __restrict__ b2,
    const float* __restrict__ W3, const float* __restrict__ b3,
    const float* __restrict__ W4, const float* __restrict__ b4,
    float* __restrict__ out, int B)
{
    __shared__ __align__(16) float sW1[120], sW2[400], sW3[400], sW4[160];
    __shared__ __align__(16) float sb1[20], sb2[20], sb3[20], sb4[8];

    const int t = threadIdx.x;
    for (int i = t; i < 120; i += NTHREADS) sW1[i] = W1[i];
    for (int i = t; i < 400; i += NTHREADS) sW2[i] = W2[i];
    for (int i = t; i < 400; i += NTHREADS) sW3[i] = W3[i];
    for (int i = t; i < 160; i += NTHREADS) sW4[i] = W4[i];
    if (t < 20) { sb1[t] = b1[t]; sb2[t] = b2[t]; sb3[t] = b3[t]; }
    if (t < 8)  { sb4[t] = b4[t]; }
    __syncthreads();

    const int row = blockIdx.x * NTHREADS + t;
    if (row >= B) return;

    // ---- input row (RHS b of the LP) ----
    float Z0, Z1, Z2, Z3, Z4, Z5;
    {
        const float2* p = (const float2*)(X + row * 6);
        float2 a0 = p[0], a1 = p[1], a2 = p[2];
        Z0 = a0.x; Z1 = a0.y; Z2 = a1.x;
        Z3 = a1.y; Z4 = a2.x; Z5 = a2.y;
    }

    // ---- MLP, f32x2-packed (validated R6-R13) ----
    float h[20], h2[20];
    {
        float Zv[6] = {Z0, Z1, Z2, Z3, Z4, Z5};
        u64 a[10];
#pragma unroll
        for (int jp = 0; jp < 10; jp++) a[jp] = *(const u64*)&sb1[2 * jp];
#pragma unroll
        for (int k = 0; k < 6; k++) {
            u64 zz = pk(Zv[k], Zv[k]);
#pragma unroll
            for (int jp = 0; jp < 10; jp++)
                a[jp] = fma2(zz, *(const u64*)&sW1[k * 20 + 2 * jp], a[jp]);
        }
#pragma unroll
        for (int jp = 0; jp < 10; jp++) {
            float s0, s1; upk(s0, s1, a[jp]);
            h[2 * jp] = fast_tanh(s0); h[2 * jp + 1] = fast_tanh(s1);
        }
    }
    {
        u64 a[10];
#pragma unroll
        for (int jp = 0; jp < 10; jp++) a[jp] = *(const u64*)&sb2[2 * jp];
#pragma unroll
        for (int k = 0; k < 20; k++) {
            u64 hh = pk(h[k], h[k]);
#pragma unroll
            for (int jp = 0; jp < 10; jp++)
                a[jp] = fma2(hh, *(const u64*)&sW2[k * 20 + 2 * jp], a[jp]);
        }
#pragma unroll
        for (int jp = 0; jp < 10; jp++) {
            float s0, s1; upk(s0, s1, a[jp]);
            h2[2 * jp] = fast_tanh(s0); h2[2 * jp + 1] = fast_tanh(s1);
        }
    }
    {
        u64 a[10];
#pragma unroll
        for (int jp = 0; jp < 10; jp++) a[jp] = *(const u64*)&sb3[2 * jp];
#pragma unroll
        for (int k = 0; k < 20; k++) {
            u64 hh = pk(h2[k], h2[k]);
#pragma unroll
            for (int jp = 0; jp < 10; jp++)
                a[jp] = fma2(hh, *(const u64*)&sW3[k * 20 + 2 * jp], a[jp]);
        }
#pragma unroll
        for (int jp = 0; jp < 10; jp++) {
            float s0, s1; upk(s0, s1, a[jp]);
            h[2 * jp] = fast_tanh(s0); h[2 * jp + 1] = fast_tanh(s1);
        }
    }
    float z[8];
    {
        u64 a[4];
#pragma unroll
        for (int jp = 0; jp < 4; jp++) a[jp] = *(const u64*)&sb4[2 * jp];
#pragma unroll
        for (int k = 0; k < 20; k++) {
            u64 hh = pk(h[k], h[k]);
#pragma unroll
            for (int jp = 0; jp < 4; jp++)
                a[jp] = fma2(hh, *(const u64*)&sW4[k * 8 + 2 * jp], a[jp]);
        }
#pragma unroll
        for (int jp = 0; jp < 4; jp++) upk(z[2 * jp], z[2 * jp + 1], a[jp]);
    }

    // ---- anti-phase stagger: warps 4-7 delay ~225 cyc (validated R13) ----
    if ((t >> 5) >= 4) {
        float acc = 1.0f;
#pragma unroll 1
        for (int i = 0; i < 56; i++)
            asm volatile("fma.rn.f32 %0, %0, 0f3F7FFF58, 0f38D1B717;" : "+f"(acc));
    }

    // ---- PDHG state init (R11/R13 body) ----
    float sdn0, sdn1, sdn2, sdn3, sdn4, sdn5, sdn6, sdn7;
    float xb0, xb1, xb2, xb3, xb4, xb5, xb6, xb7;
    float zm0, zm1, zm2, zm3, zm4, zm5, zm6, zm7;
    {
        float x00 = fmaxf(z[0], 0.0f), x01 = fmaxf(z[1], 0.0f);
        float x02 = fmaxf(z[2], 0.0f), x03 = fmaxf(z[3], 0.0f);
        float x04 = fmaxf(z[4], 0.0f), x05 = fmaxf(z[5], 0.0f);
        float x06 = fmaxf(z[6], 0.0f), x07 = fmaxf(z[7], 0.0f);
        sdn0 = x00 - z[0]; sdn1 = x01 - z[1]; sdn2 = x02 - z[2]; sdn3 = x03 - z[3];
        sdn4 = x04 - z[4]; sdn5 = x05 - z[5]; sdn6 = x06 - z[6]; sdn7 = x07 - z[7];
        xb0 = x00; xb1 = x01; xb2 = x02; xb3 = x03;
        xb4 = x04; xb5 = x05; xb6 = x06; xb7 = x07;
        zm0 = z[0] - sdn0; zm1 = z[1] - sdn1; zm2 = z[2] - sdn2; zm3 = z[3] - sdn3;
        zm4 = z[4] - sdn4; zm5 = z[5] - sdn5; zm6 = z[6] - sdn6; zm7 = z[7] - sdn7;
    }
    float y0 = 0.f, y1 = 0.f, y2 = 0.f, y3 = 0.f, y4 = 0.f, y5 = 0.f;
    float w0 = 1.f, w1 = 1.f, w2 = 1.f, w3 = 1.f,   // YIp = yI + 1
          w4 = 1.f, w5 = 1.f, w6 = 1.f, w7 = 1.f;

#pragma unroll 2
    for (int it = 0; it < PDHG_ITERS; it++) {
        // ---- s = S*xb - Z via shared pairs (17 imm-FFMA "adds") ----
        float A  = fai(xb2, xb5);
        float Bp = fai(xb1, xb4);
        float C  = fai(xb0, xb6);
        float s0 = fai(fsi(fai(xb0, xb7), Z0), A);   // ((xb0+xb7)-Z0)+A
        float s1 = fai(Bp, fsi(xb3, Z1));            // Bp+(xb3-Z1)
        float s2 = fai(C, fsi(xb1, Z2));             // C+(xb1-Z2)
        float s3 = fai(A, fsi(xb3, Z3));             // A+(xb3-Z3)
        float s4 = fai(fsi(Bp, Z4), fai(xb2, xb7));  // (Bp-Z4)+(xb2+xb7)
        float s5 = fai(C, fsi(xb4, Z5));             // C+(xb4-Z5)

        // ---- dual updates (imm-FFMA already) ----
        y0 = fmaxf(0.0f, fmaf(SGM, s0, y0));
        y1 = fmaxf(0.0f, fmaf(SGM, s1, y1));
        y2 = fmaxf(0.0f, fmaf(SGM, s2, y2));
        y3 = fmaxf(0.0f, fmaf(SGM, s3, y3));
        y4 = fmaxf(0.0f, fmaf(SGM, s4, y4));
        y5 = fmaxf(0.0f, fmaf(SGM, s5, y5));

        w0 = fmaxf(1.0f, fmaf(-SGM, xb0, w0));
        w1 = fmaxf(1.0f, fmaf(-SGM, xb1, w1));
        w2 = fmaxf(1.0f, fmaf(-SGM, xb2, w2));
        w3 = fmaxf(1.0f, fmaf(-SGM, xb3, w3));
        w4 = fmaxf(1.0f, fmaf(-SGM, xb4, w4));
        w5 = fmaxf(1.0f, fmaf(-SGM, xb5, w5));
        w6 = fmaxf(1.0f, fmaf(-SGM, xb6, w6));
        w7 = fmaxf(1.0f, fmaf(-SGM, xb7, w7));

        // ---- gy = S^T y - YIp (imm-FFMA adds/subs, q-reuse) ----
        float q25 = fai(y2, y5), q04 = fai(y0, y4), q14 = fai(y1, y4);
        float gy0 = fsi(fai(y0, q25), w0);
        float gy1 = fsi(fai(q14, y2), w1);
        float gy2 = fsi(fai(q04, y3), w2);
        float gy3 = fsi(fai(y1, y3), w3);
        float gy4 = fsi(fai(q14, y5), w4);
        float gy5 = fsi(fai(y0, y3), w5);
        float gy6 = fsi(q25, w6);
        float gy7 = fsi(q04, w7);

        // ---- d = sdn - tau*gy (imm-FFMA) ----
        float d0 = fmaf(-TAU, gy0, sdn0);
        float d1 = fmaf(-TAU, gy1, sdn1);
        float d2 = fmaf(-TAU, gy2, sdn2);
        float d3 = fmaf(-TAU, gy3, sdn3);
        float d4 = fmaf(-TAU, gy4, sdn4);
        float d5 = fmaf(-TAU, gy5, sdn5);
        float d6 = fmaf(-TAU, gy6, sdn6);
        float d7 = fmaf(-TAU, gy7, sdn7);

        // ---- ||d||^2: two 4-chains + imm-add; rsqrt; scale ----
        float na = d0 * d0;
        na = fmaf(d1, d1, na);
        na = fmaf(d2, d2, na);
        na = fmaf(d3, d3, na);
        float nb = d4 * d4;
        nb = fmaf(d5, d5, nb);
        nb = fmaf(d6, d6, nb);
        nb = fmaf(d7, d7, nb);
        float nn = fai(na, nb);
        float rr = fast_rsqrt(nn);   // nn=0 -> rr=inf -> scale=0 (exact)
        float scale = fmaxf(0.0f, fmaf(-TCC, rr, 1.0f));

        // ---- primal: ns = scale*d; xb = 2*ns + zm; zm = z - ns ----
        float ns0 = scale * d0, ns1 = scale * d1, ns2 = scale * d2, ns3 = scale * d3;
        float ns4 = scale * d4, ns5 = scale * d5, ns6 = scale * d6, ns7 = scale * d7;

        xb0 = fmaf(2.0f, ns0, zm0); zm0 = fsi(z[0], ns0); sdn0 = ns0;
        xb1 = fmaf(2.0f, ns1, zm1); zm1 = fsi(z[1], ns1); sdn1 = ns1;
        xb2 = fmaf(2.0f, ns2, zm2); zm2 = fsi(z[2], ns2); sdn2 = ns2;
        xb3 = fmaf(2.0f, ns3, zm3); zm3 = fsi(z[3], ns3); sdn3 = ns3;
        xb4 = fmaf(2.0f, ns4, zm4); zm4 = fsi(z[4], ns4); sdn4 = ns4;
        xb5 = fmaf(2.0f, ns5, zm5); zm5 = fsi(z[5], ns5); sdn5 = ns5;
        xb6 = fmaf(2.0f, ns6, zm6); zm6 = fsi(z[6], ns6); sdn6 = ns6;
        xb7 = fmaf(2.0f, ns7, zm7); zm7 = fsi(z[7], ns7); sdn7 = ns7;
    }

    // ---- x = z + sdn ----
    float4* p = (float4*)(out + row * 8);
    p[0] = make_float4(z[0] + sdn0, z[1] + sdn1, z[2] + sdn2, z[3] + sdn3);
    p[1] = make_float4(z[4] + sdn4, z[5] + sdn5, z[6] + sdn6, z[7] + sdn7);
}

extern "C" void kernel_launch(void* const* d_in, const int* in_sizes, int n_in,
                              void* d_out, int out_size) {
    const float* X  = (const float*)d_in[0];
    const float* W1 = (const float*)d_in[1];
    const float* b1 = (const float*)d_in[2];
    const float* W2 = (const float*)d_in[3];
    const float* b2 = (const float*)d_in[4];
    const float* W3 = (const float*)d_in[5];
    const float* b3 = (const float*)d_in[6];
    const float* W4 = (const float*)d_in[7];
    const float* b4 = (const float*)d_in[8];

    const int B = in_sizes[0] / 6;
    const int grid = (B + NTHREADS - 1) / NTHREADS;
    matchnet_kernel<<<grid, NTHREADS>>>(X, W1, b1, W2, b2, W3, b3, W4, b4,
                                        (float*)d_out, B);
}